// round 14
// baseline (speedup 1.0000x reference)
#include <cuda_runtime.h>
#include <math_constants.h>

typedef unsigned long long u64;
typedef unsigned int u32;

// Problem constants
#define Bb 8
#define Ll 256
#define Aa 15
#define Kk 9
#define TB 16
#define NTILES 136                     // triangular 16x16 tiles per batch
#define N_DIST_ITEMS (Bb * NTILES)     // 1088
#define N_KNN_ITEMS  256               // 32 per batch, 8 rows x 2 types each
#define N_FILL_ITEMS 680               // N_OUT/4/256
#define N_DIST_WORKERS 296             // 2 per SM
#define N_KNN_WORKERS  148             // 1 per SM
#define N_CTAS (N_DIST_WORKERS + N_KNN_WORKERS)   // 444 = full resident set

// Output layout (float32, concatenated flattened tuple)
#define OFF_BATCH   30720
#define OFF_EDGES   32768
#define OFF_ATTR    106496
#define N_OUT       696320
#define EDGES_HALF  18432
#define EDGES_ROW   36864

// Scratch
__device__ float g_d2min[Bb * Ll * Ll];
__device__ u32   g_cnt[Bb];        // dist tiles completed per batch
__device__ u32   g_done[Bb];       // knn items completed per batch (for reset)

static __device__ __forceinline__ u32 ld_acquire(const u32* p) {
    u32 v; asm volatile("ld.acquire.gpu.u32 %0, [%1];" : "=r"(v) : "l"(p) : "memory");
    return v;
}

#define CE(x, y) { u64 aa_ = x, bb_ = y; bool g_ = aa_ > bb_; x = g_ ? bb_ : aa_; y = g_ ? aa_ : bb_; }
#define SORT8(q) \
    CE(q[0],q[1]) CE(q[2],q[3]) CE(q[4],q[5]) CE(q[6],q[7]) \
    CE(q[0],q[2]) CE(q[1],q[3]) CE(q[4],q[6]) CE(q[5],q[7]) \
    CE(q[1],q[2]) CE(q[5],q[6]) \
    CE(q[0],q[4]) CE(q[1],q[5]) CE(q[2],q[6]) CE(q[3],q[7]) \
    CE(q[2],q[4]) CE(q[3],q[5]) \
    CE(q[1],q[2]) CE(q[3],q[4]) CE(q[5],q[6])

// ================= DIST item =================
static __device__ __forceinline__ void do_dist(int b, int r, const float* __restrict__ pos,
                                               float4* sI, float4* sJ, int t) {
    int ti = 0;
    while (r >= (TB - ti)) { r -= (TB - ti); ti++; }
    const int tj = ti + r;
    const int i0 = ti * TB, j0 = tj * TB;

    __syncthreads();   // protect smem reuse across loop iterations
    if (t < TB * Aa) {
        const int blk = t / Aa;
        const int at  = t % Aa;
        {
            const float* p = pos + ((size_t)((b * Ll + i0 + blk) * Aa + at)) * 3;
            float x = p[0], y = p[1], z = p[2];
            sI[t] = make_float4(x, y, z, 0.5f * (x * x + y * y + z * z));
        }
        {
            const float* p = pos + ((size_t)((b * Ll + j0 + blk) * Aa + at)) * 3;
            float x = p[0], y = p[1], z = p[2];
            sJ[t] = make_float4(x, y, z, 0.5f * (x * x + y * y + z * z));
        }
    }
    __syncthreads();

    const int ii = t >> 4;
    const int jj = t & 15;

    float jx[Aa], jy[Aa], jz[Aa], jn[Aa];
#pragma unroll
    for (int a = 0; a < Aa; a++) {
        const float4 v = sJ[jj * Aa + a];
        jx[a] = v.x; jy[a] = v.y; jz[a] = v.z; jn[a] = v.w;
    }

    float m0 = CUDART_INF_F, m1 = CUDART_INF_F;
#pragma unroll
    for (int a = 0; a < Aa; a++) {
        const float4 I = sI[ii * Aa + a];
        float mA = fmaf(-I.z, jz[0], fmaf(-I.y, jy[0], fmaf(-I.x, jx[0], jn[0])));
        float mB = fmaf(-I.z, jz[1], fmaf(-I.y, jy[1], fmaf(-I.x, jx[1], jn[1])));
#pragma unroll
        for (int c = 2; c + 1 < Aa; c += 2) {
            mA = fminf(mA, fmaf(-I.z, jz[c],   fmaf(-I.y, jy[c],   fmaf(-I.x, jx[c],   jn[c]))));
            mB = fminf(mB, fmaf(-I.z, jz[c+1], fmaf(-I.y, jy[c+1], fmaf(-I.x, jx[c+1], jn[c+1]))));
        }
        mA = fminf(mA, fmaf(-I.z, jz[Aa-1], fmaf(-I.y, jy[Aa-1], fmaf(-I.x, jx[Aa-1], jn[Aa-1]))));
        const float mloc = fminf(mA, mB) + I.w;
        if (a & 1) m1 = fminf(m1, mloc); else m0 = fminf(m0, mloc);
    }
    const float m = fmaxf(fminf(m0, m1), 0.0f);

    float* g = g_d2min + (size_t)b * Ll * Ll;
    g[(size_t)(i0 + ii) * Ll + (j0 + jj)] = m;
    g[(size_t)(j0 + jj) * Ll + (i0 + ii)] = m;

    __threadfence();          // make writes gpu-visible ...
    __syncthreads();          // ... before t0's release increment
    if (t == 0) atomicAdd(&g_cnt[b], 1u);
}

// ================= KNN item (deterministic dual-REDUX extraction) =========
static __device__ __forceinline__ void do_knn(int b, int kcta,
                                              const int* __restrict__ frag,
                                              float* __restrict__ out, int t) {
    const int lane = t & 31;
    const int l    = (kcta << 3) + (t >> 5);   // 0..255

    if (t == 0) {
        while (ld_acquire(&g_cnt[b]) < (u32)NTILES) __nanosleep(128);
    }
    __syncthreads();

    const int fi   = frag[(b << 8) + l];
    const int segi = (fi == 2) ? 1 : fi;

    const float* drow = g_d2min + ((size_t)b << 16) + ((size_t)l << 8);
    const int*   frow = frag + (b << 8);

    u64 p0[8], p1[8];
#pragma unroll
    for (int u = 0; u < 8; u++) {
        const int j  = lane + (u << 5);
        const int fj = frow[j];
        const int segj = (fj == 2) ? 1 : fj;
        const bool same = (segj == segi);
        const float v = drow[j];
        const u64 key = ((u64)__float_as_uint(v) << 32) | (u32)j;
        const u64 inf = 0xffffffff00000000ULL | (u32)j;
        p0[u] = (same && j != l) ? key : inf;   // intra
        p1[u] = (!same)          ? key : inf;   // inter
    }

    SORT8(p0)
    SORT8(p1)

    const size_t base0 = (size_t)OFF_EDGES + EDGES_ROW + (size_t)((b << 8) + l) * Kk;
    const size_t base1 = base0 + EDGES_HALF;
    const float  boff  = (float)(b << 8);

#pragma unroll
    for (int k = 0; k < Kk; k++) {
        const u32 hd0 = (u32)(p0[0] >> 32);
        const u32 hd1 = (u32)(p1[0] >> 32);
        const u32 wd0 = __reduce_min_sync(0xffffffffu, hd0);
        const u32 wd1 = __reduce_min_sync(0xffffffffu, hd1);
        const u32 cj0 = (hd0 == wd0) ? (u32)p0[0] : 0xffffffffu;
        const u32 cj1 = (hd1 == wd1) ? (u32)p1[0] : 0xffffffffu;
        const u32 wj0 = __reduce_min_sync(0xffffffffu, cj0);
        const u32 wj1 = __reduce_min_sync(0xffffffffu, cj1);
        if (lane == 0) {
            out[base0 + k] = (float)wj0 + boff;
            out[base1 + k] = (float)wj1 + boff;
        }
        if (hd0 == wd0 && (u32)p0[0] == wj0) {   // exactly one lane pops (ties resolved by index)
#pragma unroll
            for (int u = 0; u < 7; u++) p0[u] = p0[u + 1];
            p0[7] = ~0ULL;
        }
        if (hd1 == wd1 && (u32)p1[0] == wj1) {
#pragma unroll
            for (int u = 0; u < 7; u++) p1[u] = p1[u + 1];
            p1[7] = ~0ULL;
        }
    }

    __syncthreads();
    if (t == 0) {
        const u32 old = atomicAdd(&g_done[b], 1u);
        if (old == 31u) {              // last knn item of batch: reset for replay
            g_cnt[b]  = 0u;
            g_done[b] = 0u;
        }
    }
}

// ================= FILL item =================
static __device__ __forceinline__ void do_fill(int fidx, const float* __restrict__ edge_emb,
                                               float* __restrict__ out, int t) {
    const int q = (fidx << 8) + t;     // quad index
    const int i = q << 2;
    if (i >= N_OUT) return;
    float4 v;
    if (i < OFF_BATCH) {
        v.x = (float)(i / Aa); v.y = (float)((i + 1) / Aa);
        v.z = (float)((i + 2) / Aa); v.w = (float)((i + 3) / Aa);
    } else if (i < OFF_EDGES) {
        const float bv = (float)((i - OFF_BATCH) >> 8);
        v.x = bv; v.y = bv; v.z = bv; v.w = bv;
    } else if (i < OFF_ATTR) {
        const int e = i - OFF_EDGES;
        if (e >= EDGES_ROW) return;    // dst row: knn is the SOLE writer
        float s[4];
#pragma unroll
        for (int u = 0; u < 4; u++) {
            const int pu = (e + u) % EDGES_HALF;
            s[u] = (float)(((pu / Kk) % Ll) + (pu / (Ll * Kk)) * Ll);
        }
        v.x = s[0]; v.y = s[1]; v.z = s[2]; v.w = s[3];
    } else {
        const int e    = i - OFF_ATTR;
        const int type = ((e >> 4) >= EDGES_HALF) ? 1 : 0;
        v = *(const float4*)(edge_emb + type * 16 + (e & 12));
    }
    *(float4*)(out + i) = v;
}

// ---------------------------------------------------------------------------
// Role-split persistent kernel, 444 CTAs (exactly the resident set):
//   bids [0,296):   dist workers — stride the 1088 tiles batch-major, never wait
//   bids [296,444): knn/fill workers — all fill items first (useful work while
//                   dist_b0 completes), then knn items batch-major (spin per
//                   batch counter). dist (FMA-bound) and knn (MIO/latency-
//                   bound) are co-resident on every SM and overlap.
// All 444 CTAs fit simultaneously (3 x 80regs x 256thr <= 64K regs/SM), so
// the spin can never deadlock: dist workers always progress.
// ---------------------------------------------------------------------------
__global__ void __launch_bounds__(256) fused_kernel(const float* __restrict__ pos,
                                                    const int* __restrict__ frag,
                                                    const float* __restrict__ edge_emb,
                                                    float* __restrict__ out) {
    const int t = threadIdx.x;

    if (blockIdx.x < N_DIST_WORKERS) {
        __shared__ float4 sI[TB * Aa];
        __shared__ float4 sJ[TB * Aa];
        for (int item = blockIdx.x; item < N_DIST_ITEMS; item += N_DIST_WORKERS) {
            do_dist(item / NTILES, item % NTILES, pos, sI, sJ, t);
        }
    } else {
        const int w = blockIdx.x - N_DIST_WORKERS;    // 0..147
        for (int f = w; f < N_FILL_ITEMS; f += N_KNN_WORKERS) {
            do_fill(f, edge_emb, out, t);
        }
        for (int item = w; item < N_KNN_ITEMS; item += N_KNN_WORKERS) {
            do_knn(item >> 5, item & 31, frag, out, t);
        }
    }
}

// ---------------------------------------------------------------------------
extern "C" void kernel_launch(void* const* d_in, const int* in_sizes, int n_in,
                              void* d_out, int out_size) {
    const float* pos      = (const float*)d_in[0];
    const int*   frag     = (const int*)  d_in[6];
    const float* edge_emb = (const float*)d_in[7];
    float* out = (float*)d_out;

    fused_kernel<<<N_CTAS, 256>>>(pos, frag, edge_emb, out);

    (void)in_sizes; (void)n_in; (void)out_size;
}

// round 16
// speedup vs baseline: 1.0865x; 1.0865x over previous
#include <cuda_runtime.h>
#include <math_constants.h>

typedef unsigned long long u64;
typedef unsigned int u32;

// Problem constants
#define Bb 8
#define Ll 256
#define Aa 15
#define Kk 9
#define TB 16
#define NTILES 136                 // triangular 16x16 tiles
#define DIST_CTAS (Bb * NTILES)    // 1088
#define FILL_CTAS 680              // N_OUT/4/256

// Output layout (float32, concatenated flattened tuple)
#define OFF_BATCH   30720
#define OFF_EDGES   32768
#define OFF_ATTR    106496
#define N_OUT       696320
#define EDGES_HALF  18432
#define EDGES_ROW   36864

// Scratch: rank-equivalent block distance (= d2min/2, clamped >= 0), [B, L, L]
__device__ float g_d2min[Bb * Ll * Ll];

// ---------------------------------------------------------------------------
// Kernel 1: dist (triangular tiles) + static fills (round-7 proven parts).
// ---------------------------------------------------------------------------
__global__ void __launch_bounds__(256) dist_fill_kernel(const float* __restrict__ pos,
                                                        const float* __restrict__ edge_emb,
                                                        float* __restrict__ out) {
    const int t = threadIdx.x;
    if (blockIdx.x >= DIST_CTAS) {
        const int q = (blockIdx.x - DIST_CTAS) * 256 + t;   // float4 index
        const int i = q << 2;
        if (i >= N_OUT) return;
        float4 v;
        if (i < OFF_BATCH) {
            v.x = (float)(i / Aa); v.y = (float)((i + 1) / Aa);
            v.z = (float)((i + 2) / Aa); v.w = (float)((i + 3) / Aa);
        } else if (i < OFF_EDGES) {
            const float bv = (float)((i - OFF_BATCH) >> 8);
            v.x = bv; v.y = bv; v.z = bv; v.w = bv;
        } else if (i < OFF_ATTR) {
            const int e = i - OFF_EDGES;
            if (e >= EDGES_ROW) return;     // dst row: knn kernel is the SOLE writer
            float s[4];
#pragma unroll
            for (int u = 0; u < 4; u++) {
                const int pu = (e + u) % EDGES_HALF;
                s[u] = (float)(((pu / Kk) % Ll) + (pu / (Ll * Kk)) * Ll);
            }
            v.x = s[0]; v.y = s[1]; v.z = s[2]; v.w = s[3];
        } else {
            const int e    = i - OFF_ATTR;
            const int type = ((e >> 4) >= EDGES_HALF) ? 1 : 0;
            v = *(const float4*)(edge_emb + type * 16 + (e & 12));
        }
        *(float4*)(out + i) = v;
        return;
    }

    __shared__ float4 sI[TB * Aa];
    __shared__ float4 sJ[TB * Aa];

    const int b = blockIdx.x / NTILES;
    int r = blockIdx.x % NTILES, ti = 0;
    while (r >= (TB - ti)) { r -= (TB - ti); ti++; }
    const int tj = ti + r;
    const int i0 = ti * TB, j0 = tj * TB;

    if (t < TB * Aa) {
        const int blk = t / Aa;
        const int at  = t % Aa;
        {
            const float* p = pos + ((size_t)((b * Ll + i0 + blk) * Aa + at)) * 3;
            float x = p[0], y = p[1], z = p[2];
            sI[t] = make_float4(x, y, z, 0.5f * (x * x + y * y + z * z));
        }
        {
            const float* p = pos + ((size_t)((b * Ll + j0 + blk) * Aa + at)) * 3;
            float x = p[0], y = p[1], z = p[2];
            sJ[t] = make_float4(x, y, z, 0.5f * (x * x + y * y + z * z));
        }
    }
    __syncthreads();

    const int ii = t >> 4;
    const int jj = t & 15;

    float jx[Aa], jy[Aa], jz[Aa], jn[Aa];
#pragma unroll
    for (int a = 0; a < Aa; a++) {
        const float4 v = sJ[jj * Aa + a];
        jx[a] = v.x; jy[a] = v.y; jz[a] = v.z; jn[a] = v.w;
    }

    float m0 = CUDART_INF_F, m1 = CUDART_INF_F;
#pragma unroll
    for (int a = 0; a < Aa; a++) {
        const float4 I = sI[ii * Aa + a];
        float mA = fmaf(-I.z, jz[0], fmaf(-I.y, jy[0], fmaf(-I.x, jx[0], jn[0])));
        float mB = fmaf(-I.z, jz[1], fmaf(-I.y, jy[1], fmaf(-I.x, jx[1], jn[1])));
#pragma unroll
        for (int c = 2; c + 1 < Aa; c += 2) {
            mA = fminf(mA, fmaf(-I.z, jz[c],   fmaf(-I.y, jy[c],   fmaf(-I.x, jx[c],   jn[c]))));
            mB = fminf(mB, fmaf(-I.z, jz[c+1], fmaf(-I.y, jy[c+1], fmaf(-I.x, jx[c+1], jn[c+1]))));
        }
        mA = fminf(mA, fmaf(-I.z, jz[Aa-1], fmaf(-I.y, jy[Aa-1], fmaf(-I.x, jx[Aa-1], jn[Aa-1]))));
        const float mloc = fminf(mA, mB) + I.w;
        if (a & 1) m1 = fminf(m1, mloc); else m0 = fminf(m0, mloc);
    }
    const float m = fmaxf(fminf(m0, m1), 0.0f);

    float* g = g_d2min + (size_t)b * Ll * Ll;
    g[(size_t)(i0 + ii) * Ll + (j0 + jj)] = m;
    g[(size_t)(j0 + jj) * Ll + (i0 + ii)] = m;
}

// ---------------------------------------------------------------------------
// Kernel 2: merge-selection KNN. 8 lanes per (row,type) stream; 4 streams per
// warp; 1024 warps. Each lane: running sorted top-9 (u64 keys (d2<<32)|j) over
// its 32 candidates via sort8 + tent-merge(9,8)->9 per chunk (pure ALU);
// then 3-level shfl-bfly tent-merge(9,9)->9 tree within the 8-lane group.
// No REDUX. Exact tie-break (smallest j) preserved -> deterministic.
// ---------------------------------------------------------------------------
#define CE(x, y)  { u64 aa_ = x, bb_ = y; bool g_ = aa_ > bb_; x = g_ ? bb_ : aa_; y = g_ ? aa_ : bb_; }
#define MINK(x, y) ((x) < (y) ? (x) : (y))
#define SORT8A(q) \
    CE(q[0],q[1]) CE(q[2],q[3]) CE(q[4],q[5]) CE(q[6],q[7]) \
    CE(q[0],q[2]) CE(q[1],q[3]) CE(q[4],q[6]) CE(q[5],q[7]) \
    CE(q[1],q[2]) CE(q[5],q[6]) \
    CE(q[0],q[4]) CE(q[1],q[5]) CE(q[2],q[6]) CE(q[3],q[7]) \
    CE(q[2],q[4]) CE(q[3],q[5]) \
    CE(q[1],q[2]) CE(q[3],q[4]) CE(q[5],q[6])
// Sort an up-down "tent" bitonic sequence of length 9 (ascending result).
// Equivalent to front-padding with -INF to a true bitonic 16 and running the
// standard half-cleaner cascade: CE(0,8) puts the global min (an endpoint of
// any tent) at position 0; [1..8] is the bitonic remainder, cleaned by the
// power-of-two strides 4,2,1. Hand-verified on tents, monotone seqs, INF pads.
#define BITONIC9(L) \
    CE(L[0],L[8]) \
    CE(L[1],L[5]) CE(L[2],L[6]) CE(L[3],L[7]) CE(L[4],L[8]) \
    CE(L[1],L[3]) CE(L[2],L[4]) CE(L[5],L[7]) CE(L[6],L[8]) \
    CE(L[1],L[2]) CE(L[3],L[4]) CE(L[5],L[6]) CE(L[7],L[8])

__global__ void __launch_bounds__(256) knn_kernel(const int* __restrict__ frag,
                                                  float* __restrict__ out) {
    const int t     = threadIdx.x;
    const int gwarp = (blockIdx.x << 3) + (t >> 5);   // 0..1023
    const int lane  = t & 31;
    const int sid   = lane >> 3;                      // stream within warp: 0..3
    const int sub   = lane & 7;                       // lane within 8-lane group

    const int row  = (gwarp << 1) + (sid >> 1);       // 0..2047
    const int type = sid & 1;                         // 0 intra, 1 inter
    const int b    = row >> 8;
    const int l    = row & 255;

    const int fi   = frag[(b << 8) + l];
    const int segi = (fi == 2) ? 1 : fi;

    const float4* drow4 = (const float4*)(g_d2min + ((size_t)b << 16) + ((size_t)l << 8));
    const int4*   frow4 = (const int4*)(frag + (b << 8));

    u64 R[9];
#pragma unroll
    for (int c = 0; c < 4; c++) {
        const int F1 = sub + (c << 4);        // float4 index
        const int F2 = F1 + 8;
        const float4 d1 = drow4[F1];
        const float4 d2 = drow4[F2];
        const int4   f1 = frow4[F1];
        const int4   f2 = frow4[F2];

        u64 k[8];
        {
            const float dv[8] = { d1.x, d1.y, d1.z, d1.w, d2.x, d2.y, d2.z, d2.w };
            const int   fv[8] = { f1.x, f1.y, f1.z, f1.w, f2.x, f2.y, f2.z, f2.w };
#pragma unroll
            for (int e = 0; e < 8; e++) {
                const int j = ((e < 4) ? (F1 << 2) : ((F2 << 2) - 4)) + e;
                const int segj = (fv[e] == 2) ? 1 : fv[e];
                const bool same = (segj == segi);
                const bool ok = type ? (!same) : (same && j != l);
                k[e] = ok ? (((u64)__float_as_uint(dv[e]) << 32) | (u32)j)
                          : (0xffffffff00000000ULL | (u32)j);
            }
        }
        SORT8A(k)

        if (c == 0) {
#pragma unroll
            for (int e = 0; e < 8; e++) R[e] = k[e];
            R[8] = ~0ULL;
        } else {
            // merge sorted R(9) with sorted k(8), keep lowest 9:
            // L[i] = min(R[i], k[8-i]) (k[8] = +INF virtual) -> up-down tent
#pragma unroll
            for (int e = 1; e < 9; e++) R[e] = MINK(R[e], k[8 - e]);
            BITONIC9(R)
        }
    }

    // 3-level merge tree across the 8-lane group (offsets 4,2,1 stay in-group)
#pragma unroll
    for (int off = 4; off > 0; off >>= 1) {
        u64 Bx[9];
#pragma unroll
        for (int e = 0; e < 9; e++) Bx[e] = __shfl_xor_sync(0xffffffffu, R[e], off);
#pragma unroll
        for (int e = 0; e < 9; e++) R[e] = MINK(R[e], Bx[8 - e]);
        BITONIC9(R)
    }

    if (sub == 0) {
        const size_t base = (size_t)OFF_EDGES + EDGES_ROW
                          + (size_t)type * EDGES_HALF
                          + (size_t)((b << 8) + l) * Kk;
        const float boff = (float)(b << 8);
#pragma unroll
        for (int e = 0; e < 9; e++) out[base + e] = (float)((u32)R[e]) + boff;
    }
}

// ---------------------------------------------------------------------------
extern "C" void kernel_launch(void* const* d_in, const int* in_sizes, int n_in,
                              void* d_out, int out_size) {
    const float* pos      = (const float*)d_in[0];
    const int*   frag     = (const int*)  d_in[6];
    const float* edge_emb = (const float*)d_in[7];
    float* out = (float*)d_out;

    dist_fill_kernel<<<DIST_CTAS + FILL_CTAS, 256>>>(pos, edge_emb, out);
    knn_kernel<<<128, 256>>>(frag, out);

    (void)in_sizes; (void)n_in; (void)out_size;
}